// round 1
// baseline (speedup 1.0000x reference)
#include <cuda_runtime.h>
#include <math.h>

#define B_ 2
#define T_ 2048
#define C_ 1024
#define H_ 16
#define D_ 64
#define M_ (B_*T_)        // 4096
#define SCALE_ 0.125f     // 1/sqrt(64)

// Scratch (allocation-free): Q, K, V projections and attention output.
__device__ float g_Q[M_*C_];
__device__ float g_K[M_*C_];
__device__ float g_V[M_*C_];
__device__ float g_AO[M_*C_];

// ============================================================================
// SGEMM-NT: C[m][n] = sum_k A[m][k] * B[n][k]
// A: M x K row-major, B: N x K row-major (both K-contiguous), C: M x N.
// 128x128 block tile, BK=16, 8x8 per-thread register tile, 256 threads.
// ============================================================================
#define GBM 128
#define GBN 128
#define GBK 16
#define GSTRIDE (GBM + 4)   // 132: keeps float4 alignment, breaks bank conflicts

__global__ void __launch_bounds__(256)
sgemm_nt(const float* __restrict__ A, const float* __restrict__ Bm,
         float* __restrict__ Cm, int M, int N, int K)
{
    __shared__ float As[GBK][GSTRIDE];
    __shared__ float Bs[GBK][GSTRIDE];

    const int tid = threadIdx.x;
    const int bm  = blockIdx.y * GBM;
    const int bn  = blockIdx.x * GBN;
    const int tx  = tid & 15;        // 0..15 (N dir)
    const int ty  = tid >> 4;        // 0..15 (M dir)
    const int lrow = tid >> 2;       // 0..63
    const int lcol = (tid & 3) << 2; // 0,4,8,12

    float acc[8][8];
    #pragma unroll
    for (int i = 0; i < 8; i++)
        #pragma unroll
        for (int j = 0; j < 8; j++) acc[i][j] = 0.f;

    const float* Ap = A  + (long)(bm + lrow) * K + lcol;
    const float* Bp = Bm + (long)(bn + lrow) * K + lcol;

    for (int kt = 0; kt < K; kt += GBK) {
        #pragma unroll
        for (int p = 0; p < 2; p++) {
            float4 va = *(const float4*)(Ap + (long)p * 64 * K + kt);
            int r = lrow + p * 64;
            As[lcol + 0][r] = va.x;
            As[lcol + 1][r] = va.y;
            As[lcol + 2][r] = va.z;
            As[lcol + 3][r] = va.w;
            float4 vb = *(const float4*)(Bp + (long)p * 64 * K + kt);
            Bs[lcol + 0][r] = vb.x;
            Bs[lcol + 1][r] = vb.y;
            Bs[lcol + 2][r] = vb.z;
            Bs[lcol + 3][r] = vb.w;
        }
        __syncthreads();

        #pragma unroll
        for (int k = 0; k < GBK; k++) {
            float a[8], b[8];
            *(float4*)(a)     = *(const float4*)&As[k][ty * 8];
            *(float4*)(a + 4) = *(const float4*)&As[k][ty * 8 + 4];
            *(float4*)(b)     = *(const float4*)&Bs[k][tx * 8];
            *(float4*)(b + 4) = *(const float4*)&Bs[k][tx * 8 + 4];
            #pragma unroll
            for (int i = 0; i < 8; i++)
                #pragma unroll
                for (int j = 0; j < 8; j++)
                    acc[i][j] += a[i] * b[j];
        }
        __syncthreads();
    }

    #pragma unroll
    for (int i = 0; i < 8; i++) {
        float* cp = Cm + (long)(bm + ty * 8 + i) * N + bn + tx * 8;
        *(float4*)(cp)     = make_float4(acc[i][0], acc[i][1], acc[i][2], acc[i][3]);
        *(float4*)(cp + 4) = make_float4(acc[i][4], acc[i][5], acc[i][6], acc[i][7]);
    }
}

// ============================================================================
// Flash attention (causal), fp32.
// Grid: (T/64, B*H). 256 threads = 8 warps.
// Tiles: BQ=64, BKV=64, D=64. smem: Qs[64][68] + Kst[64][68] + Vs[64][68].
// Kst holds K transposed (d-major) for score phase, then is reused as P.
// Each warp owns 8 q-rows; each q-row is split across 4 lanes (16 cols each).
// ============================================================================
#define APAD 68
#define SMEM_ATTN (3 * 64 * APAD * 4)

__global__ void __launch_bounds__(256)
attn_kernel()
{
    extern __shared__ float sm[];
    float* Qs  = sm;                 // [64][APAD]  (q rows, d cols)
    float* Kst = sm + 64 * APAD;     // [64][APAD]  (d rows, c cols) -> reused as P[r][c]
    float* Vs  = sm + 2 * 64 * APAD; // [64][APAD]  (c rows, d cols)

    const int qb   = blockIdx.x;           // q tile index
    const int bh   = blockIdx.y;           // batch*head
    const int b    = bh / H_;
    const int h    = bh % H_;
    const int tid  = threadIdx.x;
    const int lane = tid & 31;
    const int warp = tid >> 5;
    const int r    = warp * 8 + (lane >> 2); // local q row 0..63
    const int c0   = (lane & 3) * 16;        // this lane's 16-col group

    // Load Q tile
    for (int idx = tid; idx < 64 * 16; idx += 256) {
        int row = idx >> 4;
        int d4  = (idx & 15) << 2;
        float4 v = *(const float4*)&g_Q[((long)(b * T_ + qb * 64 + row)) * C_ + h * D_ + d4];
        *(float4*)&Qs[row * APAD + d4] = v;
    }

    float m = -INFINITY, l = 0.f;
    float o[16];
    #pragma unroll
    for (int j = 0; j < 16; j++) o[j] = 0.f;

    for (int kb = 0; kb <= qb; kb++) {
        __syncthreads();   // prior-iteration reads of Kst/Vs done; Qs load visible
        // Load K (transposed into Kst) and V
        for (int idx = tid; idx < 64 * 16; idx += 256) {
            int row = idx >> 4;
            int d4  = (idx & 15) << 2;
            long gbase = ((long)(b * T_ + kb * 64 + row)) * C_ + h * D_ + d4;
            float4 kv = *(const float4*)&g_K[gbase];
            Kst[(d4 + 0) * APAD + row] = kv.x;
            Kst[(d4 + 1) * APAD + row] = kv.y;
            Kst[(d4 + 2) * APAD + row] = kv.z;
            Kst[(d4 + 3) * APAD + row] = kv.w;
            float4 vv = *(const float4*)&g_V[gbase];
            *(float4*)&Vs[row * APAD + d4] = vv;
        }
        __syncthreads();

        // ---- scores s[j] = sum_d Qs[r][d] * K[c0+j][d] ----
        float s[16];
        #pragma unroll
        for (int j = 0; j < 16; j++) s[j] = 0.f;

        #pragma unroll 4
        for (int d4 = 0; d4 < D_; d4 += 4) {
            float4 q = *(const float4*)&Qs[r * APAD + d4];
            const float* qf = reinterpret_cast<const float*>(&q);
            #pragma unroll
            for (int cc = 0; cc < 4; cc++) {
                float qv = qf[cc];
                const float* kp = &Kst[(d4 + cc) * APAD + c0];
                float4 k0 = *(const float4*)(kp);
                float4 k1 = *(const float4*)(kp + 4);
                float4 k2 = *(const float4*)(kp + 8);
                float4 k3 = *(const float4*)(kp + 12);
                s[0]  += qv * k0.x;  s[1]  += qv * k0.y;
                s[2]  += qv * k0.z;  s[3]  += qv * k0.w;
                s[4]  += qv * k1.x;  s[5]  += qv * k1.y;
                s[6]  += qv * k1.z;  s[7]  += qv * k1.w;
                s[8]  += qv * k2.x;  s[9]  += qv * k2.y;
                s[10] += qv * k2.z;  s[11] += qv * k2.w;
                s[12] += qv * k3.x;  s[13] += qv * k3.y;
                s[14] += qv * k3.z;  s[15] += qv * k3.w;
            }
        }

        // ---- scale + causal mask (diagonal block only) ----
        #pragma unroll
        for (int j = 0; j < 16; j++) s[j] *= SCALE_;
        if (kb == qb) {
            #pragma unroll
            for (int j = 0; j < 16; j++)
                if (c0 + j > r) s[j] = -INFINITY;
        }

        // ---- online softmax (row spread over 4 lanes) ----
        float mx = -INFINITY;
        #pragma unroll
        for (int j = 0; j < 16; j++) mx = fmaxf(mx, s[j]);
        mx = fmaxf(mx, __shfl_xor_sync(0xffffffffu, mx, 1));
        mx = fmaxf(mx, __shfl_xor_sync(0xffffffffu, mx, 2));
        float mnew  = fmaxf(m, mx);
        float alpha = __expf(m - mnew);
        float rs = 0.f;
        #pragma unroll
        for (int j = 0; j < 16; j++) {
            s[j] = __expf(s[j] - mnew);
            rs  += s[j];
        }
        rs += __shfl_xor_sync(0xffffffffu, rs, 1);
        rs += __shfl_xor_sync(0xffffffffu, rs, 2);
        l = l * alpha + rs;
        m = mnew;
        #pragma unroll
        for (int j = 0; j < 16; j++) o[j] *= alpha;

        __syncthreads();   // all Kst (K) reads done before overwrite with P
        #pragma unroll
        for (int j4 = 0; j4 < 4; j4++)
            *(float4*)&Kst[r * APAD + c0 + j4 * 4] =
                make_float4(s[j4 * 4], s[j4 * 4 + 1], s[j4 * 4 + 2], s[j4 * 4 + 3]);
        __syncthreads();

        // ---- O update: o[j] += sum_kk P[r][kk] * V[kk][c0+j] ----
        #pragma unroll 4
        for (int k4 = 0; k4 < 64; k4 += 4) {
            float4 p = *(const float4*)&Kst[r * APAD + k4];
            const float* pf = reinterpret_cast<const float*>(&p);
            #pragma unroll
            for (int cc = 0; cc < 4; cc++) {
                float pv = pf[cc];
                const float* vp = &Vs[(k4 + cc) * APAD + c0];
                float4 v0 = *(const float4*)(vp);
                float4 v1 = *(const float4*)(vp + 4);
                float4 v2 = *(const float4*)(vp + 8);
                float4 v3 = *(const float4*)(vp + 12);
                o[0]  += pv * v0.x;  o[1]  += pv * v0.y;
                o[2]  += pv * v0.z;  o[3]  += pv * v0.w;
                o[4]  += pv * v1.x;  o[5]  += pv * v1.y;
                o[6]  += pv * v1.z;  o[7]  += pv * v1.w;
                o[8]  += pv * v2.x;  o[9]  += pv * v2.y;
                o[10] += pv * v2.z;  o[11] += pv * v2.w;
                o[12] += pv * v3.x;  o[13] += pv * v3.y;
                o[14] += pv * v3.z;  o[15] += pv * v3.w;
            }
        }
    }

    // ---- finalize ----
    float inv = 1.f / l;
    int t = qb * 64 + r;
    float* op = &g_AO[((long)(b * T_ + t)) * C_ + h * D_ + c0];
    #pragma unroll
    for (int j4 = 0; j4 < 4; j4++)
        *(float4*)(op + j4 * 4) = make_float4(o[j4 * 4] * inv, o[j4 * 4 + 1] * inv,
                                              o[j4 * 4 + 2] * inv, o[j4 * 4 + 3] * inv);
}

// ============================================================================
// Launch
// ============================================================================
extern "C" void kernel_launch(void* const* d_in, const int* in_sizes, int n_in,
                              void* d_out, int out_size)
{
    const float* x  = (const float*)d_in[0];
    const float* Wq = (const float*)d_in[1];
    const float* Wk = (const float*)d_in[2];
    const float* Wv = (const float*)d_in[3];
    const float* Wo = (const float*)d_in[4];
    float* out = (float*)d_out;

    float *Q, *K, *V, *AO;
    cudaGetSymbolAddress((void**)&Q,  g_Q);
    cudaGetSymbolAddress((void**)&K,  g_K);
    cudaGetSymbolAddress((void**)&V,  g_V);
    cudaGetSymbolAddress((void**)&AO, g_AO);

    dim3 gg(C_ / GBN, M_ / GBM);   // (8, 32)

    sgemm_nt<<<gg, 256>>>(x, Wq, Q, M_, C_, C_);
    sgemm_nt<<<gg, 256>>>(x, Wk, K, M_, C_, C_);
    sgemm_nt<<<gg, 256>>>(x, Wv, V, M_, C_, C_);

    cudaFuncSetAttribute(attn_kernel, cudaFuncAttributeMaxDynamicSharedMemorySize, SMEM_ATTN);
    attn_kernel<<<dim3(T_ / 64, B_ * H_), 256, SMEM_ATTN>>>();

    sgemm_nt<<<gg, 256>>>(AO, Wo, out, M_, C_, C_);
}

// round 2
// speedup vs baseline: 6.3083x; 6.3083x over previous
#include <cuda_runtime.h>
#include <math.h>
#include <stdint.h>

#define B_ 2
#define T_ 2048
#define C_ 1024
#define H_ 16
#define D_ 64
#define M_ (B_*T_)        // 4096
#define SCALE_ 0.125f     // 1/sqrt(64)

// Scratch (allocation-free)
__device__ float g_Q[M_*C_];
__device__ float g_K[M_*C_];
__device__ float g_V[M_*C_];
__device__ float g_AO[M_*C_];

// ---------------------------------------------------------------------------
// tf32 helpers
// ---------------------------------------------------------------------------
__device__ __forceinline__ uint32_t f2tf(float x) {
    uint32_t u;
    asm("cvt.rna.tf32.f32 %0, %1;" : "=r"(u) : "f"(x));
    return u;
}

// D = A(16x8,row) * B(8x8,col) + D, tf32 in, fp32 acc
__device__ __forceinline__ void mma_tf32(float* c, const uint32_t* a, const uint32_t* b) {
    asm volatile(
        "mma.sync.aligned.m16n8k8.row.col.f32.tf32.tf32.f32 "
        "{%0,%1,%2,%3}, {%4,%5,%6,%7}, {%8,%9}, {%0,%1,%2,%3};\n"
        : "+f"(c[0]), "+f"(c[1]), "+f"(c[2]), "+f"(c[3])
        : "r"(a[0]), "r"(a[1]), "r"(a[2]), "r"(a[3]), "r"(b[0]), "r"(b[1]));
}

// ============================================================================
// GEMM-NT (tf32 tensor core): C[m][n] = sum_k A[m][k]*B[n][k]
// Block 128x128, BK=32, 256 threads = 8 warps (4m x 2n), warp tile 32x64.
// ============================================================================
#define GLD 36   // 32 + 4 pad (uint32 units)

__global__ void __launch_bounds__(256)
gemm_tf32(const float* __restrict__ A, const float* __restrict__ Bm,
          float* __restrict__ Cm, int M, int N, int K)
{
    __shared__ uint32_t As[128][GLD];
    __shared__ uint32_t Bs[128][GLD];

    const int tid  = threadIdx.x;
    const int lane = tid & 31;
    const int warp = tid >> 5;
    const int gid  = lane >> 2;   // 0..7
    const int tig  = lane & 3;    // 0..3
    const int wm   = warp & 3;    // 4 warps in M
    const int wn   = warp >> 2;   // 2 warps in N
    const int bm   = blockIdx.y * 128;
    const int bn   = blockIdx.x * 128;
    const int r0   = tid >> 3;          // 0..31
    const int c4   = (tid & 7) << 2;    // 0,4,...,28

    float acc[2][8][4];
    #pragma unroll
    for (int mt = 0; mt < 2; mt++)
        #pragma unroll
        for (int nt = 0; nt < 8; nt++)
            #pragma unroll
            for (int e = 0; e < 4; e++) acc[mt][nt][e] = 0.f;

    for (int kt = 0; kt < K; kt += 32) {
        __syncthreads();
        #pragma unroll
        for (int p = 0; p < 4; p++) {
            int row = r0 + p * 32;
            float4 va = *(const float4*)&A[(long)(bm + row) * K + kt + c4];
            uint4 ua = make_uint4(f2tf(va.x), f2tf(va.y), f2tf(va.z), f2tf(va.w));
            *(uint4*)&As[row][c4] = ua;
            float4 vb = *(const float4*)&Bm[(long)(bn + row) * K + kt + c4];
            uint4 ub = make_uint4(f2tf(vb.x), f2tf(vb.y), f2tf(vb.z), f2tf(vb.w));
            *(uint4*)&Bs[row][c4] = ub;
        }
        __syncthreads();

        #pragma unroll
        for (int ks = 0; ks < 4; ks++) {
            int k0 = ks * 8;
            uint32_t a[2][4];
            #pragma unroll
            for (int mt = 0; mt < 2; mt++) {
                int m0 = wm * 32 + mt * 16;
                a[mt][0] = As[m0 + gid][k0 + tig];
                a[mt][1] = As[m0 + 8 + gid][k0 + tig];
                a[mt][2] = As[m0 + gid][k0 + tig + 4];
                a[mt][3] = As[m0 + 8 + gid][k0 + tig + 4];
            }
            #pragma unroll
            for (int nt = 0; nt < 8; nt++) {
                int n0 = wn * 64 + nt * 8;
                uint32_t b[2];
                b[0] = Bs[n0 + gid][k0 + tig];
                b[1] = Bs[n0 + gid][k0 + tig + 4];
                mma_tf32(acc[0][nt], a[0], b);
                mma_tf32(acc[1][nt], a[1], b);
            }
        }
    }

    #pragma unroll
    for (int mt = 0; mt < 2; mt++) {
        #pragma unroll
        for (int nt = 0; nt < 8; nt++) {
            int m0 = bm + wm * 32 + mt * 16;
            int n0 = bn + wn * 64 + nt * 8 + 2 * tig;
            *(float2*)&Cm[(long)(m0 + gid) * N + n0] =
                make_float2(acc[mt][nt][0], acc[mt][nt][1]);
            *(float2*)&Cm[(long)(m0 + 8 + gid) * N + n0] =
                make_float2(acc[mt][nt][2], acc[mt][nt][3]);
        }
    }
}

// ============================================================================
// Flash attention (causal), tf32 tensor cores.
// Grid (T/64, B*H), 128 threads = 4 warps, each warp owns 16 q-rows.
// smem: Qs[64][68], Ks[64][68] (reused as P), Vs[64][68]  (tf32 bits)
// ============================================================================
#define AST 68
#define SMEM_ATTN (3 * 64 * AST * 4)

__global__ void __launch_bounds__(128)
attn_tf32()
{
    extern __shared__ uint32_t sm[];
    uint32_t* Qs = sm;                 // [64][AST]
    uint32_t* Ks = sm + 64 * AST;      // [64][AST] -> reused as P
    uint32_t* Vs = sm + 2 * 64 * AST;  // [64][AST]

    const int qb   = blockIdx.x;
    const int bh   = blockIdx.y;
    const int bb   = bh >> 4;
    const int h    = bh & 15;
    const int tid  = threadIdx.x;
    const int lane = tid & 31;
    const int warp = tid >> 5;
    const int gid  = lane >> 2;
    const int tig  = lane & 3;
    const int m0   = warp * 16;        // warp's first local q row

    // Load Q tile (convert to tf32)
    for (int idx = tid; idx < 64 * 16; idx += 128) {
        int row = idx >> 4;
        int d4  = (idx & 15) << 2;
        float4 v = *(const float4*)&g_Q[((long)(bb * T_ + qb * 64 + row)) * C_ + h * D_ + d4];
        *(uint4*)&Qs[row * AST + d4] = make_uint4(f2tf(v.x), f2tf(v.y), f2tf(v.z), f2tf(v.w));
    }

    float mr0 = -INFINITY, mr1 = -INFINITY;  // running max (rows gid, gid+8)
    float l0 = 0.f, l1 = 0.f;
    float oacc[8][4];
    #pragma unroll
    for (int nt = 0; nt < 8; nt++)
        #pragma unroll
        for (int e = 0; e < 4; e++) oacc[nt][e] = 0.f;

    for (int kb = 0; kb <= qb; kb++) {
        __syncthreads();
        for (int idx = tid; idx < 64 * 16; idx += 128) {
            int row = idx >> 4;
            int d4  = (idx & 15) << 2;
            long gb = ((long)(bb * T_ + kb * 64 + row)) * C_ + h * D_ + d4;
            float4 kv = *(const float4*)&g_K[gb];
            *(uint4*)&Ks[row * AST + d4] = make_uint4(f2tf(kv.x), f2tf(kv.y), f2tf(kv.z), f2tf(kv.w));
            float4 vv = *(const float4*)&g_V[gb];
            *(uint4*)&Vs[row * AST + d4] = make_uint4(f2tf(vv.x), f2tf(vv.y), f2tf(vv.z), f2tf(vv.w));
        }
        __syncthreads();

        // ---- S = Q @ K^T ----
        float sacc[8][4];
        #pragma unroll
        for (int nt = 0; nt < 8; nt++)
            #pragma unroll
            for (int e = 0; e < 4; e++) sacc[nt][e] = 0.f;

        #pragma unroll
        for (int ks = 0; ks < 8; ks++) {
            int k0 = ks * 8;
            uint32_t a[4];
            a[0] = Qs[(m0 + gid) * AST + k0 + tig];
            a[1] = Qs[(m0 + 8 + gid) * AST + k0 + tig];
            a[2] = Qs[(m0 + gid) * AST + k0 + tig + 4];
            a[3] = Qs[(m0 + 8 + gid) * AST + k0 + tig + 4];
            #pragma unroll
            for (int nt = 0; nt < 8; nt++) {
                uint32_t b[2];
                b[0] = Ks[(nt * 8 + gid) * AST + k0 + tig];
                b[1] = Ks[(nt * 8 + gid) * AST + k0 + tig + 4];
                mma_tf32(sacc[nt], a, b);
            }
        }

        // ---- scale + causal mask + online softmax ----
        float mx0 = -INFINITY, mx1 = -INFINITY;
        #pragma unroll
        for (int nt = 0; nt < 8; nt++) {
            #pragma unroll
            for (int e = 0; e < 4; e++) {
                float s = sacc[nt][e] * SCALE_;
                if (kb == qb) {
                    int rg = m0 + gid + ((e >> 1) << 3);
                    int cg = nt * 8 + 2 * tig + (e & 1);
                    if (cg > rg) s = -INFINITY;
                }
                sacc[nt][e] = s;
            }
            mx0 = fmaxf(mx0, fmaxf(sacc[nt][0], sacc[nt][1]));
            mx1 = fmaxf(mx1, fmaxf(sacc[nt][2], sacc[nt][3]));
        }
        mx0 = fmaxf(mx0, __shfl_xor_sync(0xffffffffu, mx0, 1));
        mx0 = fmaxf(mx0, __shfl_xor_sync(0xffffffffu, mx0, 2));
        mx1 = fmaxf(mx1, __shfl_xor_sync(0xffffffffu, mx1, 1));
        mx1 = fmaxf(mx1, __shfl_xor_sync(0xffffffffu, mx1, 2));

        float mn0 = fmaxf(mr0, mx0), mn1 = fmaxf(mr1, mx1);
        float al0 = __expf(mr0 - mn0), al1 = __expf(mr1 - mn1);
        float rs0 = 0.f, rs1 = 0.f;
        #pragma unroll
        for (int nt = 0; nt < 8; nt++) {
            sacc[nt][0] = __expf(sacc[nt][0] - mn0); rs0 += sacc[nt][0];
            sacc[nt][1] = __expf(sacc[nt][1] - mn0); rs0 += sacc[nt][1];
            sacc[nt][2] = __expf(sacc[nt][2] - mn1); rs1 += sacc[nt][2];
            sacc[nt][3] = __expf(sacc[nt][3] - mn1); rs1 += sacc[nt][3];
        }
        rs0 += __shfl_xor_sync(0xffffffffu, rs0, 1);
        rs0 += __shfl_xor_sync(0xffffffffu, rs0, 2);
        rs1 += __shfl_xor_sync(0xffffffffu, rs1, 1);
        rs1 += __shfl_xor_sync(0xffffffffu, rs1, 2);
        l0 = l0 * al0 + rs0;  l1 = l1 * al1 + rs1;
        mr0 = mn0;  mr1 = mn1;
        #pragma unroll
        for (int nt = 0; nt < 8; nt++) {
            oacc[nt][0] *= al0; oacc[nt][1] *= al0;
            oacc[nt][2] *= al1; oacc[nt][3] *= al1;
        }

        // ---- store P into Ks buffer (all warps done reading K) ----
        __syncthreads();
        #pragma unroll
        for (int nt = 0; nt < 8; nt++) {
            int c = nt * 8 + 2 * tig;
            Ks[(m0 + gid) * AST + c]         = f2tf(sacc[nt][0]);
            Ks[(m0 + gid) * AST + c + 1]     = f2tf(sacc[nt][1]);
            Ks[(m0 + 8 + gid) * AST + c]     = f2tf(sacc[nt][2]);
            Ks[(m0 + 8 + gid) * AST + c + 1] = f2tf(sacc[nt][3]);
        }
        __syncwarp();   // warp reads only its own P rows

        // ---- O += P @ V ----
        #pragma unroll
        for (int ks = 0; ks < 8; ks++) {
            int k0 = ks * 8;
            uint32_t a[4];
            a[0] = Ks[(m0 + gid) * AST + k0 + tig];
            a[1] = Ks[(m0 + 8 + gid) * AST + k0 + tig];
            a[2] = Ks[(m0 + gid) * AST + k0 + tig + 4];
            a[3] = Ks[(m0 + 8 + gid) * AST + k0 + tig + 4];
            #pragma unroll
            for (int nt = 0; nt < 8; nt++) {
                uint32_t b[2];
                b[0] = Vs[(k0 + tig) * AST + nt * 8 + gid];
                b[1] = Vs[(k0 + tig + 4) * AST + nt * 8 + gid];
                mma_tf32(oacc[nt], a, b);
            }
        }
    }

    // ---- finalize ----
    float inv0 = 1.f / l0, inv1 = 1.f / l1;
    int t0 = qb * 64 + m0 + gid;
    long base = ((long)(bb * T_) + t0) * C_ + h * D_;
    #pragma unroll
    for (int nt = 0; nt < 8; nt++) {
        int col = nt * 8 + 2 * tig;
        *(float2*)&g_AO[base + col] =
            make_float2(oacc[nt][0] * inv0, oacc[nt][1] * inv0);
        *(float2*)&g_AO[base + 8L * C_ + col] =
            make_float2(oacc[nt][2] * inv1, oacc[nt][3] * inv1);
    }
}

// ============================================================================
// Launch
// ============================================================================
extern "C" void kernel_launch(void* const* d_in, const int* in_sizes, int n_in,
                              void* d_out, int out_size)
{
    const float* x  = (const float*)d_in[0];
    const float* Wq = (const float*)d_in[1];
    const float* Wk = (const float*)d_in[2];
    const float* Wv = (const float*)d_in[3];
    const float* Wo = (const float*)d_in[4];
    float* out = (float*)d_out;

    float *Q, *K, *V, *AO;
    cudaGetSymbolAddress((void**)&Q,  g_Q);
    cudaGetSymbolAddress((void**)&K,  g_K);
    cudaGetSymbolAddress((void**)&V,  g_V);
    cudaGetSymbolAddress((void**)&AO, g_AO);

    dim3 gg(C_ / 128, M_ / 128);   // (8, 32)

    gemm_tf32<<<gg, 256>>>(x, Wq, Q, M_, C_, C_);
    gemm_tf32<<<gg, 256>>>(x, Wk, K, M_, C_, C_);
    gemm_tf32<<<gg, 256>>>(x, Wv, V, M_, C_, C_);

    cudaFuncSetAttribute(attn_tf32, cudaFuncAttributeMaxDynamicSharedMemorySize, SMEM_ATTN);
    attn_tf32<<<dim3(T_ / 64, B_ * H_), 128, SMEM_ATTN>>>();

    gemm_tf32<<<gg, 256>>>(AO, Wo, out, M_, C_, C_);
}